// round 6
// baseline (speedup 1.0000x reference)
#include <cuda_runtime.h>
#include <cuda_bf16.h>
#include <math.h>

#define N_NODES 50000
#define N_EDGES 800000
#define LN_EPS 1e-5f
#define SCAN_BLOCKS 196            // ceil(50000/256)

// ---------------- scratch (no allocations allowed -> device globals) ----------
__device__ int   g_is64;
__device__ int   g_cursor[N_NODES];
__device__ int   g_rowptr[N_NODES + 1];
__device__ int   g_cntrel[N_NODES * 2];
__device__ int   g_bsum[SCAN_BLOCKS];
__device__ int   g_boff[SCAN_BLOCKS];
__device__ float g_invcnt[N_NODES * 2];
__device__ int   g_epack[N_EDGES];              // (src<<1)|rel, CSR-ordered by dst
__device__ float g_proj1[N_NODES * 128];        // [n][r*64+c]  x@W1[r]
__device__ float g_sel1 [N_NODES * 64];         // x@root1 + b1
__device__ float g_h    [N_NODES * 64];         // layer1 output
__device__ float g_proj2[N_NODES * 128];
__device__ float g_sel2 [N_NODES * 64];

// ---------------- zero + dtype sniff (block 0 sniffs) --------------------------
// int64 edge_index has all-zero high 32-bit words (values < 50000).
__global__ void zero_sniff_kernel(const int* __restrict__ ei32) {
    int i = blockIdx.x * blockDim.x + threadIdx.x;
    if (i < N_NODES) g_cursor[i] = 0;
    if (i < 2 * N_NODES) g_cntrel[i] = 0;
    if (blockIdx.x == 0) {
        __shared__ int acc[256];
        int t = threadIdx.x;
        int v = 0;
        for (int k = t; k < 2048; k += 256) v |= ei32[2 * k + 1];
        acc[t] = v;
        __syncthreads();
        for (int off = 128; off; off >>= 1) {
            if (t < off) acc[t] |= acc[t + off];
            __syncthreads();
        }
        if (t == 0) g_is64 = (acc[0] == 0) ? 1 : 0;
    }
}

__device__ __forceinline__ int load_idx(const void* p, int i) {
    return g_is64 ? (int)((const long long*)p)[i] : ((const int*)p)[i];
}

// ---------------- CSR build ---------------------------------------------------
__global__ void count_kernel(const void* __restrict__ ei,
                             const void* __restrict__ et) {
    int e0 = (blockIdx.x * blockDim.x + threadIdx.x) * 2;
#pragma unroll
    for (int u = 0; u < 2; u++) {
        int e = e0 + u;
        if (e >= N_EDGES) return;
        int d = load_idx(ei, N_EDGES + e);
        int r = load_idx(et, e) & 1;
        d = min(max(d, 0), N_NODES - 1);
        atomicAdd(&g_cntrel[d * 2 + r], 1);
    }
}

__device__ __forceinline__ int node_cnt(int i) {
    return g_cntrel[2 * i] + g_cntrel[2 * i + 1];
}

// phase A: per-block sums of 256 node counts
__global__ void scanA_kernel() {
    __shared__ int ws[8];
    int i = blockIdx.x * 256 + threadIdx.x;
    int v = (i < N_NODES) ? node_cnt(i) : 0;
    int lane = threadIdx.x & 31, w = threadIdx.x >> 5;
#pragma unroll
    for (int off = 16; off; off >>= 1) v += __shfl_xor_sync(~0u, v, off);
    if (lane == 0) ws[w] = v;
    __syncthreads();
    if (threadIdx.x < 8) {
        int s = ws[threadIdx.x];
#pragma unroll
        for (int off = 4; off; off >>= 1) s += __shfl_xor_sync(0xffu, s, off);
        if (threadIdx.x == 0) g_bsum[blockIdx.x] = s;
    }
}

// phase B: exclusive scan of SCAN_BLOCKS partials (1 block)
__global__ void scanB_kernel() {
    __shared__ int ss[256];
    int t = threadIdx.x;
    int v = (t < SCAN_BLOCKS) ? g_bsum[t] : 0;
    ss[t] = v;
    __syncthreads();
    for (int off = 1; off < 256; off <<= 1) {
        int u = (t >= off) ? ss[t - off] : 0;
        __syncthreads();
        ss[t] += u;
        __syncthreads();
    }
    if (t < SCAN_BLOCKS) g_boff[t] = ss[t] - v;   // exclusive
    if (t == 255) g_rowptr[N_NODES] = ss[SCAN_BLOCKS - 1];
}

// phase C: in-block exclusive scan + block offset -> rowptr; also invcnt
__global__ void scanC_kernel() {
    __shared__ int ss[256];
    int t = threadIdx.x;
    int i = blockIdx.x * 256 + t;
    int v = (i < N_NODES) ? node_cnt(i) : 0;
    ss[t] = v;
    __syncthreads();
    for (int off = 1; off < 256; off <<= 1) {
        int u = (t >= off) ? ss[t - off] : 0;
        __syncthreads();
        ss[t] += u;
        __syncthreads();
    }
    if (i < N_NODES) {
        g_rowptr[i] = g_boff[blockIdx.x] + ss[t] - v;
        g_invcnt[2 * i]     = 1.0f / fmaxf((float)g_cntrel[2 * i], 1.0f);
        g_invcnt[2 * i + 1] = 1.0f / fmaxf((float)g_cntrel[2 * i + 1], 1.0f);
    }
}

__global__ void scatter_kernel(const void* __restrict__ ei,
                               const void* __restrict__ et) {
    int e0 = (blockIdx.x * blockDim.x + threadIdx.x) * 2;
#pragma unroll
    for (int u = 0; u < 2; u++) {
        int e = e0 + u;
        if (e >= N_EDGES) return;
        int s = load_idx(ei, e);
        int d = load_idx(ei, N_EDGES + e);
        int r = load_idx(et, e) & 1;
        s = min(max(s, 0), N_NODES - 1);
        d = min(max(d, 0), N_NODES - 1);
        int pos = g_rowptr[d] + atomicAdd(&g_cursor[d], 1);
        if (pos >= 0 && pos < N_EDGES) g_epack[pos] = (s << 1) | r;
    }
}

// ---------------- fused GEMM: [N,KD] @ [KD,192] -> sel[N,64], proj[N,128] -----
// cols 0..63 = root (+bias), 64..127 = W[0], 128..191 = W[1]
// 64-row x 192-col block, 256 threads, K staged in 32-slices.
// Packed fma.rn.f32x2 accumulators; weights via LDS.128 (col = 4*tx + 64*j).
template <int KD, bool USE_H, bool L2OUT>
__global__ void __launch_bounds__(256)
gemm_kernel(const float* __restrict__ Xin, const float* __restrict__ root,
            const float* __restrict__ W, const float* __restrict__ bias) {
    __shared__ __align__(16) float Ws[32 * 192];
    __shared__ __align__(16) float Xs[64 * 33];
    const float* X = USE_H ? g_h : Xin;
    float* sel  = L2OUT ? g_sel2  : g_sel1;
    float* proj = L2OUT ? g_proj2 : g_proj1;

    const int tid = threadIdx.x;
    const int row0 = blockIdx.x * 64;
    const int tx = tid & 15;     // cols: 4*tx + 64*j, j=0..2
    const int ty = tid >> 4;     // rows: ty*4 .. ty*4+3

    unsigned long long acc[4][3][2];
#pragma unroll
    for (int i = 0; i < 4; i++)
#pragma unroll
        for (int j = 0; j < 3; j++) { acc[i][j][0] = 0ull; acc[i][j][1] = 0ull; }

    for (int k0 = 0; k0 < KD; k0 += 32) {
        __syncthreads();
        for (int idx = tid; idx < 32 * 192; idx += 256) {
            int kk = idx / 192, cc = idx % 192;
            int k = k0 + kk;
            float w;
            if (cc < 64) w = root[k * 64 + cc];
            else         w = W[(((cc >> 6) - 1) * KD + k) * 64 + (cc & 63)];
            Ws[idx] = w;
        }
        for (int idx = tid; idx < 64 * 32; idx += 256) {
            int rw = idx >> 5, kk = idx & 31;
            int n = row0 + rw;
            Xs[rw * 33 + kk] = (n < N_NODES) ? X[n * KD + k0 + kk] : 0.0f;
        }
        __syncthreads();

#pragma unroll 4
        for (int kk = 0; kk < 32; kk++) {
            unsigned long long xv[4];
#pragma unroll
            for (int i = 0; i < 4; i++) {
                float xr = Xs[(ty * 4 + i) * 33 + kk];
                asm("mov.b64 %0, {%1, %1};" : "=l"(xv[i]) : "f"(xr));
            }
#pragma unroll
            for (int j = 0; j < 3; j++) {
                ulonglong2 wv =
                    *reinterpret_cast<const ulonglong2*>(&Ws[kk * 192 + 4 * tx + 64 * j]);
#pragma unroll
                for (int i = 0; i < 4; i++) {
                    asm("fma.rn.f32x2 %0, %1, %2, %0;"
                        : "+l"(acc[i][j][0]) : "l"(xv[i]), "l"(wv.x));
                    asm("fma.rn.f32x2 %0, %1, %2, %0;"
                        : "+l"(acc[i][j][1]) : "l"(xv[i]), "l"(wv.y));
                }
            }
        }
    }

    float4 b4 = *reinterpret_cast<const float4*>(&bias[4 * tx]);
#pragma unroll
    for (int i = 0; i < 4; i++) {
        int n = row0 + ty * 4 + i;
        if (n < N_NODES) {
#pragma unroll
            for (int j = 0; j < 3; j++) {
                float4 o;
                asm("mov.b64 {%0, %1}, %2;" : "=f"(o.x), "=f"(o.y) : "l"(acc[i][j][0]));
                asm("mov.b64 {%0, %1}, %2;" : "=f"(o.z), "=f"(o.w) : "l"(acc[i][j][1]));
                if (j == 0) {
                    o.x += b4.x; o.y += b4.y; o.z += b4.z; o.w += b4.w;
                    *reinterpret_cast<float4*>(&sel[n * 64 + 4 * tx]) = o;
                } else {
                    *reinterpret_cast<float4*>(&proj[n * 128 + 4 * tx + 64 * (j - 1)]) = o;
                }
            }
        }
    }
}

// ---------------- gather + mean + LayerNorm (+GELU) ---------------------------
// One warp per node; lane owns cols {2*lane, 2*lane+1} -> one LDG.64 per edge.
template <bool DO_GELU, bool L2>
__global__ void gather_kernel(const float* __restrict__ gamma,
                              const float* __restrict__ beta,
                              float* __restrict__ outp) {
    const float2* sel  = reinterpret_cast<const float2*>(L2 ? g_sel2  : g_sel1);
    const float2* proj = reinterpret_cast<const float2*>(L2 ? g_proj2 : g_proj1);
    float2* out = reinterpret_cast<float2*>(L2 ? outp : g_h);

    int warp = (blockIdx.x * blockDim.x + threadIdx.x) >> 5;
    int lane = threadIdx.x & 31;
    if (warp >= N_NODES) return;
    const int i = warp;
    int beg = g_rowptr[i], end = g_rowptr[i + 1];

    float2 a0 = make_float2(0.f, 0.f), a1 = make_float2(0.f, 0.f);
    int t = beg;
    for (; t + 8 <= end; t += 8) {
        int e[8];
        float2 v[8];
#pragma unroll
        for (int u = 0; u < 8; u++) e[u] = g_epack[t + u];
#pragma unroll
        for (int u = 0; u < 8; u++)
            v[u] = proj[(e[u] >> 1) * 64 + ((e[u] & 1) << 5) + lane];
#pragma unroll
        for (int u = 0; u < 8; u++) {
            if (e[u] & 1) { a1.x += v[u].x; a1.y += v[u].y; }
            else          { a0.x += v[u].x; a0.y += v[u].y; }
        }
    }
    for (; t < end; t++) {
        int e = g_epack[t];
        float2 v = proj[(e >> 1) * 64 + ((e & 1) << 5) + lane];
        if (e & 1) { a1.x += v.x; a1.y += v.y; }
        else       { a0.x += v.x; a0.y += v.y; }
    }

    float ic0 = g_invcnt[2 * i], ic1 = g_invcnt[2 * i + 1];
    float2 sv = sel[i * 32 + lane];
    float v0 = sv.x + a0.x * ic0 + a1.x * ic1;
    float v1 = sv.y + a0.y * ic0 + a1.y * ic1;

    float s  = v0 + v1;
    float sq = v0 * v0 + v1 * v1;
#pragma unroll
    for (int off = 16; off; off >>= 1) {
        s  += __shfl_xor_sync(0xffffffffu, s,  off);
        sq += __shfl_xor_sync(0xffffffffu, sq, off);
    }
    float mean = s * (1.0f / 64.0f);
    float var  = sq * (1.0f / 64.0f) - mean * mean;
    float inv  = rsqrtf(var + LN_EPS);
    float2 gm = reinterpret_cast<const float2*>(gamma)[lane];
    float2 bt = reinterpret_cast<const float2*>(beta)[lane];
    v0 = (v0 - mean) * inv * gm.x + bt.x;
    v1 = (v1 - mean) * inv * gm.y + bt.y;

    if (DO_GELU) {
        v0 = 0.5f * v0 * (1.0f + erff(v0 * 0.70710678118654752440f));
        v1 = 0.5f * v1 * (1.0f + erff(v1 * 0.70710678118654752440f));
    }
    out[i * 32 + lane] = make_float2(v0, v1);
}

// ---------------- launcher ----------------------------------------------------
extern "C" void kernel_launch(void* const* d_in, const int* in_sizes, int n_in,
                              void* d_out, int out_size) {
    const float* x     = (const float*)d_in[0];
    const void*  ei    = d_in[1];
    const void*  et    = d_in[2];
    const float* W1    = (const float*)d_in[3];
    const float* root1 = (const float*)d_in[4];
    const float* b1    = (const float*)d_in[5];
    const float* g1    = (const float*)d_in[6];
    const float* be1   = (const float*)d_in[7];
    const float* W2    = (const float*)d_in[8];
    const float* root2 = (const float*)d_in[9];
    const float* b2    = (const float*)d_in[10];
    const float* g2    = (const float*)d_in[11];
    const float* be2   = (const float*)d_in[12];
    float* out = (float*)d_out;

    static cudaStream_t s_aux = nullptr;
    static cudaEvent_t  ev_fork = nullptr, ev_join = nullptr;
    if (s_aux == nullptr) {
        cudaStreamCreateWithFlags(&s_aux, cudaStreamNonBlocking);
        cudaEventCreateWithFlags(&ev_fork, cudaEventDisableTiming);
        cudaEventCreateWithFlags(&ev_join, cudaEventDisableTiming);
    }

    const int GEMM_BLOCKS = (N_NODES + 63) / 64;          // 782
    const int GATH_BLOCKS = (N_NODES + 7) / 8;            // 6250 (8 warps/block)
    const int EDGE_BLOCKS = (N_EDGES / 2 + 255) / 256;    // 1563

    // ---- fork: CSR build chain on aux stream, gemm1 on main stream ----
    cudaEventRecord(ev_fork, 0);
    cudaStreamWaitEvent(s_aux, ev_fork, 0);

    zero_sniff_kernel<<<(2 * N_NODES + 255) / 256, 256, 0, s_aux>>>((const int*)ei);
    count_kernel<<<EDGE_BLOCKS, 256, 0, s_aux>>>(ei, et);
    scanA_kernel<<<SCAN_BLOCKS, 256, 0, s_aux>>>();
    scanB_kernel<<<1, 256, 0, s_aux>>>();
    scanC_kernel<<<SCAN_BLOCKS, 256, 0, s_aux>>>();
    scatter_kernel<<<EDGE_BLOCKS, 256, 0, s_aux>>>(ei, et);

    gemm_kernel<128, false, false><<<GEMM_BLOCKS, 256>>>(x, root1, W1, b1);

    // ---- join ----
    cudaEventRecord(ev_join, s_aux);
    cudaStreamWaitEvent(0, ev_join, 0);

    // ---- rest of the pipeline (serial dependencies) ----
    gather_kernel<true, false><<<GATH_BLOCKS, 256>>>(g1, be1, nullptr);
    gemm_kernel<64, true, true><<<GEMM_BLOCKS, 256>>>(nullptr, root2, W2, b2);
    gather_kernel<false, true><<<GATH_BLOCKS, 256>>>(g2, be2, out);
}

// round 8
// speedup vs baseline: 1.3529x; 1.3529x over previous
#include <cuda_runtime.h>
#include <cuda_bf16.h>
#include <cstdint>
#include <math.h>

#define N_NODES 50000
#define N_EDGES 800000
#define LN_EPS 1e-5f
#define SCAN_BLOCKS 196            // ceil(50000/256)

// ---------------- scratch (no allocations allowed -> device globals) ----------
__device__ int   g_is64;
__device__ int   g_cursor[N_NODES];
__device__ int   g_rowptr[N_NODES + 1];
__device__ int   g_cntrel[N_NODES * 2];
__device__ int   g_bsum[SCAN_BLOCKS];
__device__ int   g_boff[SCAN_BLOCKS];
__device__ float g_invcnt[N_NODES * 2];
__device__ int   g_epack[N_EDGES];              // (src<<1)|rel, CSR-ordered by dst
__device__ float g_proj1[N_NODES * 128];        // [n][r*64+c]  x@W1[r]
__device__ float g_sel1 [N_NODES * 64];         // x@root1 + b1
__device__ float g_h    [N_NODES * 64];         // layer1 output
__device__ float g_proj2[N_NODES * 128];
__device__ float g_sel2 [N_NODES * 64];

// ---------------- zero + dtype sniff (block 0 sniffs) --------------------------
__global__ void zero_sniff_kernel(const int* __restrict__ ei32) {
    int i = blockIdx.x * blockDim.x + threadIdx.x;
    if (i < N_NODES) g_cursor[i] = 0;
    if (i < 2 * N_NODES) g_cntrel[i] = 0;
    if (blockIdx.x == 0) {
        __shared__ int acc[256];
        int t = threadIdx.x;
        int v = 0;
        for (int k = t; k < 2048; k += 256) v |= ei32[2 * k + 1];
        acc[t] = v;
        __syncthreads();
        for (int off = 128; off; off >>= 1) {
            if (t < off) acc[t] |= acc[t + off];
            __syncthreads();
        }
        if (t == 0) g_is64 = (acc[0] == 0) ? 1 : 0;
    }
}

__device__ __forceinline__ int load_idx(const void* p, int i) {
    return g_is64 ? (int)((const long long*)p)[i] : ((const int*)p)[i];
}

// ---------------- CSR build ---------------------------------------------------
__global__ void count_kernel(const void* __restrict__ ei,
                             const void* __restrict__ et) {
    int e0 = (blockIdx.x * blockDim.x + threadIdx.x) * 2;
#pragma unroll
    for (int u = 0; u < 2; u++) {
        int e = e0 + u;
        if (e >= N_EDGES) return;
        int d = load_idx(ei, N_EDGES + e);
        int r = load_idx(et, e) & 1;
        d = min(max(d, 0), N_NODES - 1);
        atomicAdd(&g_cntrel[d * 2 + r], 1);
    }
}

__device__ __forceinline__ int node_cnt(int i) {
    return g_cntrel[2 * i] + g_cntrel[2 * i + 1];
}

__global__ void scanA_kernel() {
    __shared__ int ws[8];
    int i = blockIdx.x * 256 + threadIdx.x;
    int v = (i < N_NODES) ? node_cnt(i) : 0;
    int lane = threadIdx.x & 31, w = threadIdx.x >> 5;
#pragma unroll
    for (int off = 16; off; off >>= 1) v += __shfl_xor_sync(~0u, v, off);
    if (lane == 0) ws[w] = v;
    __syncthreads();
    if (threadIdx.x < 8) {
        int s = ws[threadIdx.x];
#pragma unroll
        for (int off = 4; off; off >>= 1) s += __shfl_xor_sync(0xffu, s, off);
        if (threadIdx.x == 0) g_bsum[blockIdx.x] = s;
    }
}

__global__ void scanB_kernel() {
    __shared__ int ss[256];
    int t = threadIdx.x;
    int v = (t < SCAN_BLOCKS) ? g_bsum[t] : 0;
    ss[t] = v;
    __syncthreads();
    for (int off = 1; off < 256; off <<= 1) {
        int u = (t >= off) ? ss[t - off] : 0;
        __syncthreads();
        ss[t] += u;
        __syncthreads();
    }
    if (t < SCAN_BLOCKS) g_boff[t] = ss[t] - v;
    if (t == 255) g_rowptr[N_NODES] = ss[SCAN_BLOCKS - 1];
}

__global__ void scanC_kernel() {
    __shared__ int ss[256];
    int t = threadIdx.x;
    int i = blockIdx.x * 256 + t;
    int v = (i < N_NODES) ? node_cnt(i) : 0;
    ss[t] = v;
    __syncthreads();
    for (int off = 1; off < 256; off <<= 1) {
        int u = (t >= off) ? ss[t - off] : 0;
        __syncthreads();
        ss[t] += u;
        __syncthreads();
    }
    if (i < N_NODES) {
        g_rowptr[i] = g_boff[blockIdx.x] + ss[t] - v;
        g_invcnt[2 * i]     = 1.0f / fmaxf((float)g_cntrel[2 * i], 1.0f);
        g_invcnt[2 * i + 1] = 1.0f / fmaxf((float)g_cntrel[2 * i + 1], 1.0f);
    }
}

__global__ void scatter_kernel(const void* __restrict__ ei,
                               const void* __restrict__ et) {
    int e0 = (blockIdx.x * blockDim.x + threadIdx.x) * 2;
#pragma unroll
    for (int u = 0; u < 2; u++) {
        int e = e0 + u;
        if (e >= N_EDGES) return;
        int s = load_idx(ei, e);
        int d = load_idx(ei, N_EDGES + e);
        int r = load_idx(et, e) & 1;
        s = min(max(s, 0), N_NODES - 1);
        d = min(max(d, 0), N_NODES - 1);
        int pos = g_rowptr[d] + atomicAdd(&g_cursor[d], 1);
        if (pos >= 0 && pos < N_EDGES) g_epack[pos] = (s << 1) | r;
    }
}

// ---------------- cp.async helpers --------------------------------------------
__device__ __forceinline__ void cp16(unsigned int saddr, const void* gaddr, int srcbytes) {
    asm volatile("cp.async.ca.shared.global [%0], [%1], 16, %2;\n"
                 :: "r"(saddr), "l"(gaddr), "r"(srcbytes));
}
__device__ __forceinline__ void cp_commit() {
    asm volatile("cp.async.commit_group;\n");
}
template <int N>
__device__ __forceinline__ void cp_wait() {
    asm volatile("cp.async.wait_group %0;\n" :: "n"(N));
}

// ---------------- fused GEMM: [rows,KD] @ [KD,192] -> sel[.,64], proj[.,128] --
// cols 0..63 = root (+bias), 64..127 = W[0], 128..191 = W[1]
// 64-row x 192-col block, 256 threads, K in 16-chunks, cp.async double buffer.
// Packed fma.rn.f32x2 accumulators.
template <int KD, bool USE_H, bool L2OUT>
__global__ void __launch_bounds__(256)
gemm_kernel(const float* __restrict__ Xin, const float* __restrict__ root,
            const float* __restrict__ W, const float* __restrict__ bias,
            int blk0) {
    __shared__ __align__(16) float Ws[2][16 * 192];
    __shared__ __align__(16) float Xs[2][64 * 16];
    const float* X = USE_H ? g_h : Xin;
    float* sel  = L2OUT ? g_sel2  : g_sel1;
    float* proj = L2OUT ? g_proj2 : g_proj1;

    const int tid = threadIdx.x;
    const int row0 = (blk0 + blockIdx.x) * 64;
    const int tx = tid & 15;     // cols: 4*tx + 64*j, j=0..2
    const int ty = tid >> 4;     // rows: ty*4 .. ty*4+3
    constexpr int NCHUNK = KD / 16;

    // per-thread fixed staging assignments
    // Ws: 768 16B-chunks -> 3 per thread
    int wq[3], wkk[3];
#pragma unroll
    for (int u = 0; u < 3; u++) {
        int q = tid + 256 * u;
        wkk[u] = q / 48;
        wq[u] = (q % 48) * 4;          // cc4
    }
    // Xs: 256 16B-chunks -> 1 per thread
    const int xrw = tid >> 2;
    const int xseg = (tid & 3) * 4;
    const int xn = row0 + xrw;
    const bool xok = (xn < N_NODES);

    auto issue = [&](int c, int b) {
        int k0 = c * 16;
#pragma unroll
        for (int u = 0; u < 3; u++) {
            int k = k0 + wkk[u];
            int cc4 = wq[u];
            const float* src;
            if (cc4 < 64) src = root + k * 64 + cc4;
            else          src = W + ((size_t)(((cc4 >> 6) - 1) * KD + k)) * 64 + (cc4 & 63);
            unsigned int da = (unsigned int)__cvta_generic_to_shared(&Ws[b][wkk[u] * 192 + cc4]);
            cp16(da, src, 16);
        }
        {
            const float* src = X + (size_t)xn * KD + k0 + xseg;
            unsigned int da = (unsigned int)__cvta_generic_to_shared(&Xs[b][xrw * 16 + xseg]);
            cp16(da, src, xok ? 16 : 0);
        }
        cp_commit();
    };

    unsigned long long acc[4][3][2];
#pragma unroll
    for (int i = 0; i < 4; i++)
#pragma unroll
        for (int j = 0; j < 3; j++) { acc[i][j][0] = 0ull; acc[i][j][1] = 0ull; }

    issue(0, 0);
    for (int c = 0; c < NCHUNK; c++) {
        int b = c & 1;
        if (c + 1 < NCHUNK) {
            issue(c + 1, b ^ 1);
            cp_wait<1>();
        } else {
            cp_wait<0>();
        }
        __syncthreads();

#pragma unroll 4
        for (int kk = 0; kk < 16; kk++) {
            unsigned long long xv[4];
#pragma unroll
            for (int i = 0; i < 4; i++) {
                float xr = Xs[b][(ty * 4 + i) * 16 + kk];
                asm("mov.b64 %0, {%1, %1};" : "=l"(xv[i]) : "f"(xr));
            }
#pragma unroll
            for (int j = 0; j < 3; j++) {
                ulonglong2 wv =
                    *reinterpret_cast<const ulonglong2*>(&Ws[b][kk * 192 + 4 * tx + 64 * j]);
#pragma unroll
                for (int i = 0; i < 4; i++) {
                    asm("fma.rn.f32x2 %0, %1, %2, %0;"
                        : "+l"(acc[i][j][0]) : "l"(xv[i]), "l"(wv.x));
                    asm("fma.rn.f32x2 %0, %1, %2, %0;"
                        : "+l"(acc[i][j][1]) : "l"(xv[i]), "l"(wv.y));
                }
            }
        }
        __syncthreads();   // buffer b will be overwritten two iterations later
    }

    float4 b4 = *reinterpret_cast<const float4*>(&bias[4 * tx]);
#pragma unroll
    for (int i = 0; i < 4; i++) {
        int n = row0 + ty * 4 + i;
        if (n < N_NODES) {
#pragma unroll
            for (int j = 0; j < 3; j++) {
                float4 o;
                asm("mov.b64 {%0, %1}, %2;" : "=f"(o.x), "=f"(o.y) : "l"(acc[i][j][0]));
                asm("mov.b64 {%0, %1}, %2;" : "=f"(o.z), "=f"(o.w) : "l"(acc[i][j][1]));
                if (j == 0) {
                    o.x += b4.x; o.y += b4.y; o.z += b4.z; o.w += b4.w;
                    *reinterpret_cast<float4*>(&sel[n * 64 + 4 * tx]) = o;
                } else {
                    *reinterpret_cast<float4*>(&proj[n * 128 + 4 * tx + 64 * (j - 1)]) = o;
                }
            }
        }
    }
}

// ---------------- gather + mean + LayerNorm (+GELU) ---------------------------
// One warp per node; lane owns cols {2*lane, 2*lane+1} -> one LDG.64 per edge.
template <bool DO_GELU, bool L2>
__global__ void gather_kernel(const float* __restrict__ gamma,
                              const float* __restrict__ beta,
                              float* __restrict__ outp, int node0) {
    const float2* sel  = reinterpret_cast<const float2*>(L2 ? g_sel2  : g_sel1);
    const float2* proj = reinterpret_cast<const float2*>(L2 ? g_proj2 : g_proj1);
    float2* out = reinterpret_cast<float2*>(L2 ? outp : g_h);

    int warp = (blockIdx.x * blockDim.x + threadIdx.x) >> 5;
    int lane = threadIdx.x & 31;
    const int i = node0 + warp;
    if (i >= N_NODES) return;
    int beg = g_rowptr[i], end = g_rowptr[i + 1];

    float2 a0 = make_float2(0.f, 0.f), a1 = make_float2(0.f, 0.f);
    int t = beg;
    for (; t + 8 <= end; t += 8) {
        int e[8];
        float2 v[8];
#pragma unroll
        for (int u = 0; u < 8; u++) e[u] = g_epack[t + u];
#pragma unroll
        for (int u = 0; u < 8; u++)
            v[u] = proj[(e[u] >> 1) * 64 + ((e[u] & 1) << 5) + lane];
#pragma unroll
        for (int u = 0; u < 8; u++) {
            if (e[u] & 1) { a1.x += v[u].x; a1.y += v[u].y; }
            else          { a0.x += v[u].x; a0.y += v[u].y; }
        }
    }
    for (; t < end; t++) {
        int e = g_epack[t];
        float2 v = proj[(e >> 1) * 64 + ((e & 1) << 5) + lane];
        if (e & 1) { a1.x += v.x; a1.y += v.y; }
        else       { a0.x += v.x; a0.y += v.y; }
    }

    float ic0 = g_invcnt[2 * i], ic1 = g_invcnt[2 * i + 1];
    float2 sv = sel[i * 32 + lane];
    float v0 = sv.x + a0.x * ic0 + a1.x * ic1;
    float v1 = sv.y + a0.y * ic0 + a1.y * ic1;

    float s  = v0 + v1;
    float sq = v0 * v0 + v1 * v1;
#pragma unroll
    for (int off = 16; off; off >>= 1) {
        s  += __shfl_xor_sync(0xffffffffu, s,  off);
        sq += __shfl_xor_sync(0xffffffffu, sq, off);
    }
    float mean = s * (1.0f / 64.0f);
    float var  = sq * (1.0f / 64.0f) - mean * mean;
    float inv  = rsqrtf(var + LN_EPS);
    float2 gm = reinterpret_cast<const float2*>(gamma)[lane];
    float2 bt = reinterpret_cast<const float2*>(beta)[lane];
    v0 = (v0 - mean) * inv * gm.x + bt.x;
    v1 = (v1 - mean) * inv * gm.y + bt.y;

    if (DO_GELU) {
        v0 = 0.5f * v0 * (1.0f + erff(v0 * 0.70710678118654752440f));
        v1 = 0.5f * v1 * (1.0f + erff(v1 * 0.70710678118654752440f));
    }
    out[i * 32 + lane] = make_float2(v0, v1);
}

// ---------------- launcher ----------------------------------------------------
extern "C" void kernel_launch(void* const* d_in, const int* in_sizes, int n_in,
                              void* d_out, int out_size) {
    const float* x     = (const float*)d_in[0];
    const void*  ei    = d_in[1];
    const void*  et    = d_in[2];
    const float* W1    = (const float*)d_in[3];
    const float* root1 = (const float*)d_in[4];
    const float* b1    = (const float*)d_in[5];
    const float* g1    = (const float*)d_in[6];
    const float* be1   = (const float*)d_in[7];
    const float* W2    = (const float*)d_in[8];
    const float* root2 = (const float*)d_in[9];
    const float* b2    = (const float*)d_in[10];
    const float* g2    = (const float*)d_in[11];
    const float* be2   = (const float*)d_in[12];
    float* out = (float*)d_out;

    static cudaStream_t s_aux = nullptr;
    static cudaEvent_t  ev_fork = nullptr, ev_csr = nullptr, ev_g1 = nullptr, ev_b = nullptr;
    if (s_aux == nullptr) {
        cudaStreamCreateWithFlags(&s_aux, cudaStreamNonBlocking);
        cudaEventCreateWithFlags(&ev_fork, cudaEventDisableTiming);
        cudaEventCreateWithFlags(&ev_csr, cudaEventDisableTiming);
        cudaEventCreateWithFlags(&ev_g1, cudaEventDisableTiming);
        cudaEventCreateWithFlags(&ev_b, cudaEventDisableTiming);
    }

    const int GEMM_BLOCKS = (N_NODES + 63) / 64;          // 782
    const int GEMM_A = 391, GEMM_B = GEMM_BLOCKS - GEMM_A; // rows split at 25024
    const int GATH_BLOCKS = (N_NODES + 7) / 8;            // 6250
    const int GATH_A = 3128, GATH_B = GATH_BLOCKS - GATH_A; // nodes split at 25024
    const int EDGE_BLOCKS = (N_EDGES / 2 + 255) / 256;    // 1563

    // ---- fork: CSR build chain on aux stream, gemm1 on main stream ----
    cudaEventRecord(ev_fork, 0);
    cudaStreamWaitEvent(s_aux, ev_fork, 0);

    zero_sniff_kernel<<<(2 * N_NODES + 255) / 256, 256, 0, s_aux>>>((const int*)ei);
    count_kernel<<<EDGE_BLOCKS, 256, 0, s_aux>>>(ei, et);
    scanA_kernel<<<SCAN_BLOCKS, 256, 0, s_aux>>>();
    scanB_kernel<<<1, 256, 0, s_aux>>>();
    scanC_kernel<<<SCAN_BLOCKS, 256, 0, s_aux>>>();
    scatter_kernel<<<EDGE_BLOCKS, 256, 0, s_aux>>>(ei, et);
    cudaEventRecord(ev_csr, s_aux);

    gemm_kernel<128, false, false><<<GEMM_BLOCKS, 256>>>(x, root1, W1, b1, 0);
    cudaEventRecord(ev_g1, 0);

    // ---- pipelined middle: gather1/gemm2 split at node 25024 ----
    cudaStreamWaitEvent(0, ev_csr, 0);          // main: needs CSR for gather1_A
    cudaStreamWaitEvent(s_aux, ev_g1, 0);       // aux: needs gemm1 for gather1_B

    gather_kernel<true, false><<<GATH_A, 256>>>(g1, be1, nullptr, 0);
    gather_kernel<true, false><<<GATH_B, 256, 0, s_aux>>>(g1, be1, nullptr, 25024);

    gemm_kernel<64, true, true><<<GEMM_A, 256>>>(nullptr, root2, W2, b2, 0);
    gemm_kernel<64, true, true><<<GEMM_B, 256, 0, s_aux>>>(nullptr, root2, W2, b2, GEMM_A);

    // ---- join + final gather ----
    cudaEventRecord(ev_b, s_aux);
    cudaStreamWaitEvent(0, ev_b, 0);
    gather_kernel<false, true><<<GATH_BLOCKS, 256>>>(g2, be2, out, 0);
}

// round 10
// speedup vs baseline: 1.4812x; 1.0949x over previous
#include <cuda_runtime.h>
#include <cuda_bf16.h>
#include <cstdint>
#include <math.h>

#define N_NODES 50000
#define N_EDGES 800000
#define LN_EPS 1e-5f
#define SCAN_BLOCKS 196            // ceil(50000/256)

// ---------------- scratch (no allocations allowed -> device globals) ----------
__device__ int   g_is64;
__device__ int   g_cursor[N_NODES];
__device__ int   g_rowptr[N_NODES + 1];
__device__ int   g_cntrel[N_NODES * 2];
__device__ int   g_bsum[SCAN_BLOCKS];
__device__ int   g_boff[SCAN_BLOCKS];
__device__ float g_invcnt[N_NODES * 2];
__device__ int   g_epack[N_EDGES];              // (src<<1)|rel, CSR-ordered by dst
__device__ float g_proj1[N_NODES * 128];        // [n][r*64+c]  x@W1[r]
__device__ float g_sel1 [N_NODES * 64];         // x@root1 + b1
__device__ float g_proj2[N_NODES * 128];
__device__ float g_sel2 [N_NODES * 64];
// split-bf16 operands
__device__ __nv_bfloat16 g_Xh[N_NODES * 128];
__device__ __nv_bfloat16 g_Xl[N_NODES * 128];
__device__ __nv_bfloat16 g_Hh[N_NODES * 64];
__device__ __nv_bfloat16 g_Hl[N_NODES * 64];
__device__ __nv_bfloat16 g_W1h[192 * 128];      // [n][k] k-contig (n = output col)
__device__ __nv_bfloat16 g_W1l[192 * 128];
__device__ __nv_bfloat16 g_W2h[192 * 64];
__device__ __nv_bfloat16 g_W2l[192 * 64];

// ---------------- zero + dtype sniff (block 0 sniffs) --------------------------
__global__ void zero_sniff_kernel(const int* __restrict__ ei32) {
    int i = blockIdx.x * blockDim.x + threadIdx.x;
    if (i < N_NODES) g_cursor[i] = 0;
    if (i < 2 * N_NODES) g_cntrel[i] = 0;
    if (blockIdx.x == 0) {
        __shared__ int acc[256];
        int t = threadIdx.x;
        int v = 0;
        for (int k = t; k < 2048; k += 256) v |= ei32[2 * k + 1];
        acc[t] = v;
        __syncthreads();
        for (int off = 128; off; off >>= 1) {
            if (t < off) acc[t] |= acc[t + off];
            __syncthreads();
        }
        if (t == 0) g_is64 = (acc[0] == 0) ? 1 : 0;
    }
}

__device__ __forceinline__ int load_idx(const void* p, int i) {
    return g_is64 ? (int)((const long long*)p)[i] : ((const int*)p)[i];
}

// ---------------- CSR build ---------------------------------------------------
__global__ void count_kernel(const void* __restrict__ ei,
                             const void* __restrict__ et) {
    int e0 = (blockIdx.x * blockDim.x + threadIdx.x) * 2;
#pragma unroll
    for (int u = 0; u < 2; u++) {
        int e = e0 + u;
        if (e >= N_EDGES) return;
        int d = load_idx(ei, N_EDGES + e);
        int r = load_idx(et, e) & 1;
        d = min(max(d, 0), N_NODES - 1);
        atomicAdd(&g_cntrel[d * 2 + r], 1);
    }
}

__device__ __forceinline__ int node_cnt(int i) {
    return g_cntrel[2 * i] + g_cntrel[2 * i + 1];
}

__global__ void scanA_kernel() {
    __shared__ int ws[8];
    int i = blockIdx.x * 256 + threadIdx.x;
    int v = (i < N_NODES) ? node_cnt(i) : 0;
    int lane = threadIdx.x & 31, w = threadIdx.x >> 5;
#pragma unroll
    for (int off = 16; off; off >>= 1) v += __shfl_xor_sync(~0u, v, off);
    if (lane == 0) ws[w] = v;
    __syncthreads();
    if (threadIdx.x < 8) {
        int s = ws[threadIdx.x];
#pragma unroll
        for (int off = 4; off; off >>= 1) s += __shfl_xor_sync(0xffu, s, off);
        if (threadIdx.x == 0) g_bsum[blockIdx.x] = s;
    }
}

__global__ void scanB_kernel() {
    __shared__ int ss[256];
    int t = threadIdx.x;
    int v = (t < SCAN_BLOCKS) ? g_bsum[t] : 0;
    ss[t] = v;
    __syncthreads();
    for (int off = 1; off < 256; off <<= 1) {
        int u = (t >= off) ? ss[t - off] : 0;
        __syncthreads();
        ss[t] += u;
        __syncthreads();
    }
    if (t < SCAN_BLOCKS) g_boff[t] = ss[t] - v;
    if (t == 255) g_rowptr[N_NODES] = ss[SCAN_BLOCKS - 1];
}

__global__ void scanC_kernel() {
    __shared__ int ss[256];
    int t = threadIdx.x;
    int i = blockIdx.x * 256 + t;
    int v = (i < N_NODES) ? node_cnt(i) : 0;
    ss[t] = v;
    __syncthreads();
    for (int off = 1; off < 256; off <<= 1) {
        int u = (t >= off) ? ss[t - off] : 0;
        __syncthreads();
        ss[t] += u;
        __syncthreads();
    }
    if (i < N_NODES) {
        g_rowptr[i] = g_boff[blockIdx.x] + ss[t] - v;
        g_invcnt[2 * i]     = 1.0f / fmaxf((float)g_cntrel[2 * i], 1.0f);
        g_invcnt[2 * i + 1] = 1.0f / fmaxf((float)g_cntrel[2 * i + 1], 1.0f);
    }
}

__global__ void scatter_kernel(const void* __restrict__ ei,
                               const void* __restrict__ et) {
    int e0 = (blockIdx.x * blockDim.x + threadIdx.x) * 2;
#pragma unroll
    for (int u = 0; u < 2; u++) {
        int e = e0 + u;
        if (e >= N_EDGES) return;
        int s = load_idx(ei, e);
        int d = load_idx(ei, N_EDGES + e);
        int r = load_idx(et, e) & 1;
        s = min(max(s, 0), N_NODES - 1);
        d = min(max(d, 0), N_NODES - 1);
        int pos = g_rowptr[d] + atomicAdd(&g_cursor[d], 1);
        if (pos >= 0 && pos < N_EDGES) g_epack[pos] = (s << 1) | r;
    }
}

// ---------------- split prep kernels ------------------------------------------
__device__ __forceinline__ void split_bf16(float v, __nv_bfloat16& h, __nv_bfloat16& l) {
    h = __float2bfloat16_rn(v);
    l = __float2bfloat16_rn(v - __bfloat162float(h));
}

// x [N,128] fp32 -> g_Xh/g_Xl bf16 (same layout)
__global__ void xsplit_kernel(const float* __restrict__ x) {
    int base = (blockIdx.x * blockDim.x + threadIdx.x) * 4;
    if (base >= N_NODES * 128) return;
    float4 v = *reinterpret_cast<const float4*>(&x[base]);
    __nv_bfloat16 h0, h1, h2, h3, l0, l1, l2, l3;
    split_bf16(v.x, h0, l0); split_bf16(v.y, h1, l1);
    split_bf16(v.z, h2, l2); split_bf16(v.w, h3, l3);
    reinterpret_cast<__nv_bfloat162*>(g_Xh)[base / 2]     = __nv_bfloat162(h0, h1);
    reinterpret_cast<__nv_bfloat162*>(g_Xh)[base / 2 + 1] = __nv_bfloat162(h2, h3);
    reinterpret_cast<__nv_bfloat162*>(g_Xl)[base / 2]     = __nv_bfloat162(l0, l1);
    reinterpret_cast<__nv_bfloat162*>(g_Xl)[base / 2 + 1] = __nv_bfloat162(l2, l3);
}

// weights [root|W0|W1] -> Wh/Wl [192][KD] (k contiguous)
template <int KD, bool L2>
__global__ void wsplit_kernel(const float* __restrict__ root, const float* __restrict__ W) {
    __nv_bfloat16* Wh = L2 ? g_W2h : g_W1h;
    __nv_bfloat16* Wl = L2 ? g_W2l : g_W1l;
    int idx = blockIdx.x * blockDim.x + threadIdx.x;
    if (idx >= 192 * KD) return;
    int n = idx / KD, k = idx % KD;
    float w;
    if (n < 64) w = root[k * 64 + n];
    else        w = W[(((n >> 6) - 1) * KD + k) * 64 + (n & 63)];
    __nv_bfloat16 h, l;
    split_bf16(w, h, l);
    Wh[idx] = h;
    Wl[idx] = l;
}

// ---------------- cp.async helpers --------------------------------------------
__device__ __forceinline__ void cp16(unsigned int saddr, const void* gaddr, int srcbytes) {
    asm volatile("cp.async.ca.shared.global [%0], [%1], 16, %2;\n"
                 :: "r"(saddr), "l"(gaddr), "r"(srcbytes));
}
__device__ __forceinline__ void cp_commit() {
    asm volatile("cp.async.commit_group;\n");
}
template <int N>
__device__ __forceinline__ void cp_wait() {
    asm volatile("cp.async.wait_group %0;\n" :: "n"(N));
}

__device__ __forceinline__ void mma16816(float* d, const uint32_t* a, uint32_t b0, uint32_t b1) {
    asm volatile(
        "mma.sync.aligned.m16n8k16.row.col.f32.bf16.bf16.f32 "
        "{%0,%1,%2,%3}, {%4,%5,%6,%7}, {%8,%9}, {%0,%1,%2,%3};\n"
        : "+f"(d[0]), "+f"(d[1]), "+f"(d[2]), "+f"(d[3])
        : "r"(a[0]), "r"(a[1]), "r"(a[2]), "r"(a[3]), "r"(b0), "r"(b1));
}

// ---------------- split-bf16 tensor-core GEMM ---------------------------------
// D[64x192] = X[64xKD] @ Wall[KDx192];  D = AhBh + AhBl + AlBh (fp32 accum)
// 256 thr = 8 warps; warp tile 16 rows x 96 cols (12 n-tiles of m16n8k16).
// smem rows padded to 24 elems (48B): conflict-free + 16B-aligned cp.async.
template <int KD, bool USE_H, bool L2OUT>
__global__ void __launch_bounds__(256)
gemm_kernel(const float* __restrict__ bias, int blk0) {
    __shared__ __align__(16) __nv_bfloat16 Bs[2][2][192 * 24];
    __shared__ __align__(16) __nv_bfloat16 As[2][2][64 * 24];
    const __nv_bfloat16* Xh = USE_H ? g_Hh : g_Xh;
    const __nv_bfloat16* Xl = USE_H ? g_Hl : g_Xl;
    const __nv_bfloat16* Wh = L2OUT ? g_W2h : g_W1h;
    const __nv_bfloat16* Wl = L2OUT ? g_W2l : g_W1l;
    float* sel  = L2OUT ? g_sel2  : g_sel1;
    float* proj = L2OUT ? g_proj2 : g_proj1;

    const int tid = threadIdx.x;
    const int row0 = (blk0 + blockIdx.x) * 64;
    const int wid = tid >> 5, lane = tid & 31;
    const int wr = wid & 3;          // row band: wr*16
    const int wc = wid >> 2;         // col band: wc*96
    const int g = lane >> 2, t = lane & 3;
    constexpr int NCHUNK = KD / 16;

    auto issue = [&](int c, int b) {
        int k0 = c * 16;
#pragma unroll
        for (int u = 0; u < 4; u++) {
            int q = tid + (u << 8);
            if (q < 768) {
                int half = (q >= 384) ? 1 : 0;
                int rem = q - half * 384;                 // FIX: 384 not pow2; was q & 383
                int n = rem >> 1, seg = rem & 1;
                const __nv_bfloat16* src = (half ? Wl : Wh) + n * KD + k0 + seg * 8;
                unsigned int da = (unsigned int)__cvta_generic_to_shared(&Bs[b][half][n * 24 + seg * 8]);
                cp16(da, src, 16);
            } else {
                int rem = q - 768;
                int half = (rem >= 128) ? 1 : 0;
                int r2 = rem & 127;
                int row = r2 >> 1, seg = r2 & 1;
                int n = row0 + row;
                const __nv_bfloat16* src = (half ? Xl : Xh) + (size_t)n * KD + k0 + seg * 8;
                unsigned int da = (unsigned int)__cvta_generic_to_shared(&As[b][half][row * 24 + seg * 8]);
                cp16(da, src, n < N_NODES ? 16 : 0);
            }
        }
        cp_commit();
    };

    float d[12][4];
#pragma unroll
    for (int j = 0; j < 12; j++)
#pragma unroll
        for (int q = 0; q < 4; q++) d[j][q] = 0.0f;

    issue(0, 0);
    for (int c = 0; c < NCHUNK; c++) {
        int b = c & 1;
        if (c + 1 < NCHUNK) {
            issue(c + 1, b ^ 1);
            cp_wait<1>();
        } else {
            cp_wait<0>();
        }
        __syncthreads();

        const uint32_t* Ah32 = reinterpret_cast<const uint32_t*>(&As[b][0][0]);
        const uint32_t* Al32 = reinterpret_cast<const uint32_t*>(&As[b][1][0]);
        const uint32_t* Bh32 = reinterpret_cast<const uint32_t*>(&Bs[b][0][0]);
        const uint32_t* Bl32 = reinterpret_cast<const uint32_t*>(&Bs[b][1][0]);

        // A fragments (PTX m16n8k16 row-major mapping), rows = wr*16 + {g, g+8}
        int ra = (wr * 16 + g) * 12 + t;        // 24 elems = 12 words per row
        uint32_t ah[4], al[4];
        ah[0] = Ah32[ra];            ah[1] = Ah32[ra + 96];       // +8 rows = +96 words
        ah[2] = Ah32[ra + 4];        ah[3] = Ah32[ra + 96 + 4];   // k+8 = +4 words
        al[0] = Al32[ra];            al[1] = Al32[ra + 96];
        al[2] = Al32[ra + 4];        al[3] = Al32[ra + 96 + 4];

#pragma unroll
        for (int j = 0; j < 12; j++) {
            int rb = (wc * 96 + j * 8 + g) * 12 + t;
            uint32_t bh0 = Bh32[rb], bh1 = Bh32[rb + 4];
            uint32_t bl0 = Bl32[rb], bl1 = Bl32[rb + 4];
            mma16816(d[j], ah, bh0, bh1);
            mma16816(d[j], ah, bl0, bl1);
            mma16816(d[j], al, bh0, bh1);
        }
        __syncthreads();
    }

    // epilogue: c0,c1 -> row (wr*16+g), cols 2t,2t+1; c2,c3 -> row +8
    int r0 = row0 + wr * 16 + g;
    int r1 = r0 + 8;
#pragma unroll
    for (int j = 0; j < 12; j++) {
        int cc = wc * 96 + j * 8 + 2 * t;
        float2 p0 = make_float2(d[j][0], d[j][1]);
        float2 p1 = make_float2(d[j][2], d[j][3]);
        if (cc < 64) {
            float2 b2 = *reinterpret_cast<const float2*>(&bias[cc]);
            p0.x += b2.x; p0.y += b2.y;
            p1.x += b2.x; p1.y += b2.y;
            if (r0 < N_NODES) *reinterpret_cast<float2*>(&sel[r0 * 64 + cc]) = p0;
            if (r1 < N_NODES) *reinterpret_cast<float2*>(&sel[r1 * 64 + cc]) = p1;
        } else {
            if (r0 < N_NODES) *reinterpret_cast<float2*>(&proj[r0 * 128 + cc - 64]) = p0;
            if (r1 < N_NODES) *reinterpret_cast<float2*>(&proj[r1 * 128 + cc - 64]) = p1;
        }
    }
}

// ---------------- gather + mean + LayerNorm (+GELU) ---------------------------
// One warp per node; lane owns cols {2*lane, 2*lane+1} -> one LDG.64 per edge.
// Layer1 (!L2): writes split bf16 h (g_Hh/g_Hl). Layer2: writes fp32 out.
template <bool DO_GELU, bool L2>
__global__ void gather_kernel(const float* __restrict__ gamma,
                              const float* __restrict__ beta,
                              float* __restrict__ outp, int node0) {
    const float2* sel  = reinterpret_cast<const float2*>(L2 ? g_sel2  : g_sel1);
    const float2* proj = reinterpret_cast<const float2*>(L2 ? g_proj2 : g_proj1);

    int warp = (blockIdx.x * blockDim.x + threadIdx.x) >> 5;
    int lane = threadIdx.x & 31;
    const int i = node0 + warp;
    if (i >= N_NODES) return;
    int beg = g_rowptr[i], end = g_rowptr[i + 1];

    float2 a0 = make_float2(0.f, 0.f), a1 = make_float2(0.f, 0.f);
    int t = beg;
    for (; t + 8 <= end; t += 8) {
        int e[8];
        float2 v[8];
#pragma unroll
        for (int u = 0; u < 8; u++) e[u] = g_epack[t + u];
#pragma unroll
        for (int u = 0; u < 8; u++)
            v[u] = proj[(e[u] >> 1) * 64 + ((e[u] & 1) << 5) + lane];
#pragma unroll
        for (int u = 0; u < 8; u++) {
            if (e[u] & 1) { a1.x += v[u].x; a1.y += v[u].y; }
            else          { a0.x += v[u].x; a0.y += v[u].y; }
        }
    }
    for (; t < end; t++) {
        int e = g_epack[t];
        float2 v = proj[(e >> 1) * 64 + ((e & 1) << 5) + lane];
        if (e & 1) { a1.x += v.x; a1.y += v.y; }
        else       { a0.x += v.x; a0.y += v.y; }
    }

    float ic0 = g_invcnt[2 * i], ic1 = g_invcnt[2 * i + 1];
    float2 sv = sel[i * 32 + lane];
    float v0 = sv.x + a0.x * ic0 + a1.x * ic1;
    float v1 = sv.y + a0.y * ic0 + a1.y * ic1;

    float s  = v0 + v1;
    float sq = v0 * v0 + v1 * v1;
#pragma unroll
    for (int off = 16; off; off >>= 1) {
        s  += __shfl_xor_sync(0xffffffffu, s,  off);
        sq += __shfl_xor_sync(0xffffffffu, sq, off);
    }
    float mean = s * (1.0f / 64.0f);
    float var  = sq * (1.0f / 64.0f) - mean * mean;
    float inv  = rsqrtf(var + LN_EPS);
    float2 gm = reinterpret_cast<const float2*>(gamma)[lane];
    float2 bt = reinterpret_cast<const float2*>(beta)[lane];
    v0 = (v0 - mean) * inv * gm.x + bt.x;
    v1 = (v1 - mean) * inv * gm.y + bt.y;

    if (DO_GELU) {
        v0 = 0.5f * v0 * (1.0f + erff(v0 * 0.70710678118654752440f));
        v1 = 0.5f * v1 * (1.0f + erff(v1 * 0.70710678118654752440f));
    }

    if (L2) {
        reinterpret_cast<float2*>(outp)[i * 32 + lane] = make_float2(v0, v1);
    } else {
        __nv_bfloat16 h0, h1, l0, l1;
        split_bf16(v0, h0, l0);
        split_bf16(v1, h1, l1);
        reinterpret_cast<__nv_bfloat162*>(g_Hh)[i * 32 + lane] = __nv_bfloat162(h0, h1);
        reinterpret_cast<__nv_bfloat162*>(g_Hl)[i * 32 + lane] = __nv_bfloat162(l0, l1);
    }
}

// ---------------- launcher ----------------------------------------------------
extern "C" void kernel_launch(void* const* d_in, const int* in_sizes, int n_in,
                              void* d_out, int out_size) {
    const float* x     = (const float*)d_in[0];
    const void*  ei    = d_in[1];
    const void*  et    = d_in[2];
    const float* W1    = (const float*)d_in[3];
    const float* root1 = (const float*)d_in[4];
    const float* b1    = (const float*)d_in[5];
    const float* g1    = (const float*)d_in[6];
    const float* be1   = (const float*)d_in[7];
    const float* W2    = (const float*)d_in[8];
    const float* root2 = (const float*)d_in[9];
    const float* b2    = (const float*)d_in[10];
    const float* g2    = (const float*)d_in[11];
    const float* be2   = (const float*)d_in[12];
    float* out = (float*)d_out;

    static cudaStream_t s_aux = nullptr;
    static cudaEvent_t  ev_fork = nullptr, ev_csr = nullptr, ev_g1 = nullptr, ev_b = nullptr;
    if (s_aux == nullptr) {
        cudaStreamCreateWithFlags(&s_aux, cudaStreamNonBlocking);
        cudaEventCreateWithFlags(&ev_fork, cudaEventDisableTiming);
        cudaEventCreateWithFlags(&ev_csr, cudaEventDisableTiming);
        cudaEventCreateWithFlags(&ev_g1, cudaEventDisableTiming);
        cudaEventCreateWithFlags(&ev_b, cudaEventDisableTiming);
    }

    const int GEMM_BLOCKS = (N_NODES + 63) / 64;          // 782
    const int GEMM_A = 391, GEMM_B = GEMM_BLOCKS - GEMM_A;
    const int GATH_BLOCKS = (N_NODES + 7) / 8;            // 6250
    const int GATH_A = 3128, GATH_B = GATH_BLOCKS - GATH_A;
    const int EDGE_BLOCKS = (N_EDGES / 2 + 255) / 256;    // 1563

    // ---- fork: CSR chain + wsplit2 on aux; xsplit + wsplit1 + gemm1 on main --
    cudaEventRecord(ev_fork, 0);
    cudaStreamWaitEvent(s_aux, ev_fork, 0);

    zero_sniff_kernel<<<(2 * N_NODES + 255) / 256, 256, 0, s_aux>>>((const int*)ei);
    count_kernel<<<EDGE_BLOCKS, 256, 0, s_aux>>>(ei, et);
    scanA_kernel<<<SCAN_BLOCKS, 256, 0, s_aux>>>();
    scanB_kernel<<<1, 256, 0, s_aux>>>();
    scanC_kernel<<<SCAN_BLOCKS, 256, 0, s_aux>>>();
    scatter_kernel<<<EDGE_BLOCKS, 256, 0, s_aux>>>(ei, et);
    wsplit_kernel<64, true><<<(192 * 64 + 255) / 256, 256, 0, s_aux>>>(root2, W2);
    cudaEventRecord(ev_csr, s_aux);

    wsplit_kernel<128, false><<<(192 * 128 + 255) / 256, 256>>>(root1, W1);
    xsplit_kernel<<<(N_NODES * 128 / 4 + 255) / 256, 256>>>(x);
    gemm_kernel<128, false, false><<<GEMM_BLOCKS, 256>>>(b1, 0);
    cudaEventRecord(ev_g1, 0);

    // ---- pipelined middle: gather1/gemm2 split at node 25024 ----
    cudaStreamWaitEvent(0, ev_csr, 0);
    cudaStreamWaitEvent(s_aux, ev_g1, 0);

    gather_kernel<true, false><<<GATH_A, 256>>>(g1, be1, nullptr, 0);
    gather_kernel<true, false><<<GATH_B, 256, 0, s_aux>>>(g1, be1, nullptr, 25024);

    gemm_kernel<64, true, true><<<GEMM_A, 256>>>(b2, 0);
    gemm_kernel<64, true, true><<<GEMM_B, 256, 0, s_aux>>>(b2, GEMM_A);

    // ---- join + final gather ----
    cudaEventRecord(ev_b, s_aux);
    cudaStreamWaitEvent(0, ev_b, 0);
    gather_kernel<false, true><<<GATH_BLOCKS, 256>>>(g2, be2, out, 0);
}

// round 11
// speedup vs baseline: 1.6170x; 1.0917x over previous
#include <cuda_runtime.h>
#include <cuda_bf16.h>
#include <cstdint>
#include <math.h>

#define N_NODES 50000
#define N_EDGES 800000
#define LN_EPS 1e-5f
#define SCAN_BLOCKS 196            // ceil(50000/256)

// ---------------- scratch (no allocations allowed -> device globals) ----------
__device__ int   g_is64;
__device__ int   g_scan_done;
__device__ int   g_cursor[N_NODES * 2];
__device__ int   g_rowptr[N_NODES + 1];
__device__ int   g_cntrel[N_NODES * 2];
__device__ int   g_bsum[SCAN_BLOCKS];
__device__ int   g_boff[SCAN_BLOCKS];
__device__ float g_invcnt[N_NODES * 2];
__device__ int   g_epack[N_EDGES];              // src, CSR-ordered by dst, rel-segmented
__device__ float g_proj1[N_NODES * 128];        // [n][r*64+c]  x@W1[r]
__device__ float g_sel1 [N_NODES * 64];         // x@root1 + b1
__device__ float g_h    [N_NODES * 64];         // layer1 output (fp32)
__device__ float g_proj2[N_NODES * 128];
__device__ float g_sel2 [N_NODES * 64];
// split-bf16 weights [n][k] k-contig (n = output col; [root|W0|W1])
__device__ __nv_bfloat16 g_W1h[192 * 128];
__device__ __nv_bfloat16 g_W1l[192 * 128];
__device__ __nv_bfloat16 g_W2h[192 * 64];
__device__ __nv_bfloat16 g_W2l[192 * 64];

// ---------------- zero + dtype sniff (block 0 sniffs) --------------------------
__global__ void zero_sniff_kernel(const int* __restrict__ ei32) {
    int i = blockIdx.x * blockDim.x + threadIdx.x;
    if (i < 2 * N_NODES) { g_cursor[i] = 0; g_cntrel[i] = 0; }
    if (i == 0) g_scan_done = 0;
    if (blockIdx.x == 0) {
        __shared__ int acc[256];
        int t = threadIdx.x;
        int v = 0;
        for (int k = t; k < 2048; k += 256) v |= ei32[2 * k + 1];
        acc[t] = v;
        __syncthreads();
        for (int off = 128; off; off >>= 1) {
            if (t < off) acc[t] |= acc[t + off];
            __syncthreads();
        }
        if (t == 0) g_is64 = (acc[0] == 0) ? 1 : 0;
    }
}

__device__ __forceinline__ int load_idx(const void* p, int i) {
    return g_is64 ? (int)((const long long*)p)[i] : ((const int*)p)[i];
}

// ---------------- CSR build ---------------------------------------------------
__global__ void count_kernel(const void* __restrict__ ei,
                             const void* __restrict__ et) {
    int e0 = (blockIdx.x * blockDim.x + threadIdx.x) * 2;
#pragma unroll
    for (int u = 0; u < 2; u++) {
        int e = e0 + u;
        if (e >= N_EDGES) return;
        int d = load_idx(ei, N_EDGES + e);
        int r = load_idx(et, e) & 1;
        d = min(max(d, 0), N_NODES - 1);
        atomicAdd(&g_cntrel[d * 2 + r], 1);
    }
}

__device__ __forceinline__ int node_cnt(int i) {
    return g_cntrel[2 * i] + g_cntrel[2 * i + 1];
}

// phase A (per-block sums) + phase B (exclusive scan of partials) in last block
__global__ void scanAB_kernel() {
    __shared__ int ws[8];
    __shared__ int is_last;
    int i = blockIdx.x * 256 + threadIdx.x;
    int v = (i < N_NODES) ? node_cnt(i) : 0;
    int lane = threadIdx.x & 31, w = threadIdx.x >> 5;
#pragma unroll
    for (int off = 16; off; off >>= 1) v += __shfl_xor_sync(~0u, v, off);
    if (lane == 0) ws[w] = v;
    __syncthreads();
    if (threadIdx.x < 8) {
        int s = ws[threadIdx.x];
#pragma unroll
        for (int off = 4; off; off >>= 1) s += __shfl_xor_sync(0xffu, s, off);
        if (threadIdx.x == 0) {
            g_bsum[blockIdx.x] = s;
            __threadfence();
            int c = atomicAdd(&g_scan_done, 1);
            is_last = (c == gridDim.x - 1);
        }
    }
    __syncthreads();
    if (!is_last) return;
    // phase B
    __shared__ int ss[256];
    int t = threadIdx.x;
    int b = (t < SCAN_BLOCKS) ? g_bsum[t] : 0;
    ss[t] = b;
    __syncthreads();
    for (int off = 1; off < 256; off <<= 1) {
        int u = (t >= off) ? ss[t - off] : 0;
        __syncthreads();
        ss[t] += u;
        __syncthreads();
    }
    if (t < SCAN_BLOCKS) g_boff[t] = ss[t] - b;   // exclusive
    if (t == 255) g_rowptr[N_NODES] = ss[SCAN_BLOCKS - 1];
}

// phase C: in-block exclusive scan + block offset -> rowptr; also invcnt
__global__ void scanC_kernel() {
    __shared__ int ss[256];
    int t = threadIdx.x;
    int i = blockIdx.x * 256 + t;
    int v = (i < N_NODES) ? node_cnt(i) : 0;
    ss[t] = v;
    __syncthreads();
    for (int off = 1; off < 256; off <<= 1) {
        int u = (t >= off) ? ss[t - off] : 0;
        __syncthreads();
        ss[t] += u;
        __syncthreads();
    }
    if (i < N_NODES) {
        g_rowptr[i] = g_boff[blockIdx.x] + ss[t] - v;
        g_invcnt[2 * i]     = 1.0f / fmaxf((float)g_cntrel[2 * i], 1.0f);
        g_invcnt[2 * i + 1] = 1.0f / fmaxf((float)g_cntrel[2 * i + 1], 1.0f);
    }
}

// relation-segmented scatter: rel0 edges first, then rel1, within each node
__global__ void scatter_kernel(const void* __restrict__ ei,
                               const void* __restrict__ et) {
    int e0 = (blockIdx.x * blockDim.x + threadIdx.x) * 2;
#pragma unroll
    for (int u = 0; u < 2; u++) {
        int e = e0 + u;
        if (e >= N_EDGES) return;
        int s = load_idx(ei, e);
        int d = load_idx(ei, N_EDGES + e);
        int r = load_idx(et, e) & 1;
        s = min(max(s, 0), N_NODES - 1);
        d = min(max(d, 0), N_NODES - 1);
        int base = g_rowptr[d] + (r ? g_cntrel[2 * d] : 0);
        int pos = base + atomicAdd(&g_cursor[2 * d + r], 1);
        if (pos >= 0 && pos < N_EDGES) g_epack[pos] = s;
    }
}

// ---------------- weight split (both layers, one launch) -----------------------
__device__ __forceinline__ void split_bf16(float v, __nv_bfloat16& h, __nv_bfloat16& l) {
    h = __float2bfloat16_rn(v);
    l = __float2bfloat16_rn(v - __bfloat162float(h));
}

__global__ void wsplit_all_kernel(const float* __restrict__ root1, const float* __restrict__ W1,
                                  const float* __restrict__ root2, const float* __restrict__ W2) {
    int idx = blockIdx.x * blockDim.x + threadIdx.x;
    if (idx < 192 * 128) {
        int n = idx / 128, k = idx % 128;
        float w;
        if (n < 64) w = root1[k * 64 + n];
        else        w = W1[(((n >> 6) - 1) * 128 + k) * 64 + (n & 63)];
        __nv_bfloat16 h, l;
        split_bf16(w, h, l);
        g_W1h[idx] = h;
        g_W1l[idx] = l;
    } else if (idx < 192 * 128 + 192 * 64) {
        int i2 = idx - 192 * 128;
        int n = i2 / 64, k = i2 % 64;
        float w;
        if (n < 64) w = root2[k * 64 + n];
        else        w = W2[(((n >> 6) - 1) * 64 + k) * 64 + (n & 63)];
        __nv_bfloat16 h, l;
        split_bf16(w, h, l);
        g_W2h[i2] = h;
        g_W2l[i2] = l;
    }
}

// ---------------- cp.async helpers --------------------------------------------
__device__ __forceinline__ void cp16(unsigned int saddr, const void* gaddr, int srcbytes) {
    asm volatile("cp.async.ca.shared.global [%0], [%1], 16, %2;\n"
                 :: "r"(saddr), "l"(gaddr), "r"(srcbytes));
}
__device__ __forceinline__ void cp_commit() {
    asm volatile("cp.async.commit_group;\n");
}
template <int N>
__device__ __forceinline__ void cp_wait() {
    asm volatile("cp.async.wait_group %0;\n" :: "n"(N));
}

__device__ __forceinline__ void mma16816(float* d, const uint32_t* a, uint32_t b0, uint32_t b1) {
    asm volatile(
        "mma.sync.aligned.m16n8k16.row.col.f32.bf16.bf16.f32 "
        "{%0,%1,%2,%3}, {%4,%5,%6,%7}, {%8,%9}, {%0,%1,%2,%3};\n"
        : "+f"(d[0]), "+f"(d[1]), "+f"(d[2]), "+f"(d[3])
        : "r"(a[0]), "r"(a[1]), "r"(a[2]), "r"(a[3]), "r"(b0), "r"(b1));
}

__device__ __forceinline__ void split_pack(float2 v, uint32_t& h, uint32_t& l) {
    __nv_bfloat16 hx, lx, hy, ly;
    split_bf16(v.x, hx, lx);
    split_bf16(v.y, hy, ly);
    __nv_bfloat162 hh(hx, hy), ll(lx, ly);
    h = *reinterpret_cast<uint32_t*>(&hh);
    l = *reinterpret_cast<uint32_t*>(&ll);
}

// ---------------- split-bf16 tensor-core GEMM (A = fp32, split in-register) ----
// D[64x192] = X[64xKD] @ Wall[KDx192];  D = AhBh + AhBl + AlBh (fp32 accum)
// 256 thr = 8 warps; warp tile 16 rows x 96 cols (12 n-tiles of m16n8k16).
// B smem rows padded to 24 bf16; A smem rows padded to 24 fp32 (conflict-free).
template <int KD, bool USE_H, bool L2OUT>
__global__ void __launch_bounds__(256)
gemm_kernel(const float* __restrict__ Xin, const float* __restrict__ bias, int blk0) {
    __shared__ __align__(16) __nv_bfloat16 Bs[2][2][192 * 24];
    __shared__ __align__(16) float As[2][64 * 24];
    const float* X = USE_H ? g_h : Xin;
    const __nv_bfloat16* Wh = L2OUT ? g_W2h : g_W1h;
    const __nv_bfloat16* Wl = L2OUT ? g_W2l : g_W1l;
    float* sel  = L2OUT ? g_sel2  : g_sel1;
    float* proj = L2OUT ? g_proj2 : g_proj1;

    const int tid = threadIdx.x;
    const int row0 = (blk0 + blockIdx.x) * 64;
    const int wid = tid >> 5, lane = tid & 31;
    const int wr = wid & 3;          // row band: wr*16
    const int wc = wid >> 2;         // col band: wc*96
    const int g = lane >> 2, t = lane & 3;
    constexpr int NCHUNK = KD / 16;

    auto issue = [&](int c, int b) {
        int k0 = c * 16;
#pragma unroll
        for (int u = 0; u < 4; u++) {
            int q = tid + (u << 8);
            if (q < 768) {
                int half = (q >= 384) ? 1 : 0;
                int rem = q - half * 384;
                int n = rem >> 1, seg = rem & 1;
                const __nv_bfloat16* src = (half ? Wl : Wh) + n * KD + k0 + seg * 8;
                unsigned int da = (unsigned int)__cvta_generic_to_shared(&Bs[b][half][n * 24 + seg * 8]);
                cp16(da, src, 16);
            } else {
                int rem = q - 768;             // 0..255
                int row = rem >> 2, seg = rem & 3;
                int n = row0 + row;
                const float* src = X + (size_t)n * KD + k0 + seg * 4;
                unsigned int da = (unsigned int)__cvta_generic_to_shared(&As[b][row * 24 + seg * 4]);
                cp16(da, src, n < N_NODES ? 16 : 0);
            }
        }
        cp_commit();
    };

    float d[12][4];
#pragma unroll
    for (int j = 0; j < 12; j++)
#pragma unroll
        for (int q = 0; q < 4; q++) d[j][q] = 0.0f;

    issue(0, 0);
    for (int c = 0; c < NCHUNK; c++) {
        int b = c & 1;
        if (c + 1 < NCHUNK) {
            issue(c + 1, b ^ 1);
            cp_wait<1>();
        } else {
            cp_wait<0>();
        }
        __syncthreads();

        // build split-bf16 A fragments from fp32 smem
        const float* Af = As[b];
        int rlo = (wr * 16 + g) * 24;
        int rhi = rlo + 8 * 24;
        float2 v00 = *reinterpret_cast<const float2*>(&Af[rlo + 2 * t]);       // a0: row g,   k 2t..2t+1
        float2 v10 = *reinterpret_cast<const float2*>(&Af[rhi + 2 * t]);       // a1: row g+8
        float2 v01 = *reinterpret_cast<const float2*>(&Af[rlo + 2 * t + 8]);   // a2: row g,   k+8
        float2 v11 = *reinterpret_cast<const float2*>(&Af[rhi + 2 * t + 8]);   // a3: row g+8, k+8
        uint32_t ah[4], al[4];
        split_pack(v00, ah[0], al[0]);
        split_pack(v10, ah[1], al[1]);
        split_pack(v01, ah[2], al[2]);
        split_pack(v11, ah[3], al[3]);

        const uint32_t* Bh32 = reinterpret_cast<const uint32_t*>(&Bs[b][0][0]);
        const uint32_t* Bl32 = reinterpret_cast<const uint32_t*>(&Bs[b][1][0]);
#pragma unroll
        for (int j = 0; j < 12; j++) {
            int rb = (wc * 96 + j * 8 + g) * 12 + t;
            uint32_t bh0 = Bh32[rb], bh1 = Bh32[rb + 4];
            uint32_t bl0 = Bl32[rb], bl1 = Bl32[rb + 4];
            mma16816(d[j], ah, bh0, bh1);
            mma16816(d[j], ah, bl0, bl1);
            mma16816(d[j], al, bh0, bh1);
        }
        __syncthreads();
    }

    // epilogue: c0,c1 -> row (wr*16+g), cols 2t,2t+1; c2,c3 -> row +8
    int r0 = row0 + wr * 16 + g;
    int r1 = r0 + 8;
#pragma unroll
    for (int j = 0; j < 12; j++) {
        int cc = wc * 96 + j * 8 + 2 * t;
        float2 p0 = make_float2(d[j][0], d[j][1]);
        float2 p1 = make_float2(d[j][2], d[j][3]);
        if (cc < 64) {
            float2 b2 = *reinterpret_cast<const float2*>(&bias[cc]);
            p0.x += b2.x; p0.y += b2.y;
            p1.x += b2.x; p1.y += b2.y;
            if (r0 < N_NODES) *reinterpret_cast<float2*>(&sel[r0 * 64 + cc]) = p0;
            if (r1 < N_NODES) *reinterpret_cast<float2*>(&sel[r1 * 64 + cc]) = p1;
        } else {
            if (r0 < N_NODES) *reinterpret_cast<float2*>(&proj[r0 * 128 + cc - 64]) = p0;
            if (r1 < N_NODES) *reinterpret_cast<float2*>(&proj[r1 * 128 + cc - 64]) = p1;
        }
    }
}

// ---------------- gather + mean + LayerNorm (+GELU) ---------------------------
// One warp per node; lane owns cols {2*lane, 2*lane+1} -> one LDG.64 per edge.
// Edge list is relation-segmented: [beg,mid) rel0, [mid,end) rel1 -> no predication.
template <bool DO_GELU, bool L2>
__global__ void gather_kernel(const float* __restrict__ gamma,
                              const float* __restrict__ beta,
                              float* __restrict__ outp, int node0) {
    const float2* sel  = reinterpret_cast<const float2*>(L2 ? g_sel2  : g_sel1);
    const float2* proj = reinterpret_cast<const float2*>(L2 ? g_proj2 : g_proj1);
    float2* out = reinterpret_cast<float2*>(L2 ? outp : g_h);

    int warp = (blockIdx.x * blockDim.x + threadIdx.x) >> 5;
    int lane = threadIdx.x & 31;
    const int i = node0 + warp;
    if (i >= N_NODES) return;
    int beg = g_rowptr[i], end = g_rowptr[i + 1];
    int mid = beg + g_cntrel[2 * i];

    float2 a0 = make_float2(0.f, 0.f), a1 = make_float2(0.f, 0.f);

    // relation 0 segment
    int t = beg;
    for (; t + 8 <= mid; t += 8) {
        int e[8];
        float2 v[8];
#pragma unroll
        for (int u = 0; u < 8; u++) e[u] = g_epack[t + u];
#pragma unroll
        for (int u = 0; u < 8; u++) v[u] = proj[e[u] * 64 + lane];
#pragma unroll
        for (int u = 0; u < 8; u++) { a0.x += v[u].x; a0.y += v[u].y; }
    }
    for (; t < mid; t++) {
        float2 v = proj[g_epack[t] * 64 + lane];
        a0.x += v.x; a0.y += v.y;
    }
    // relation 1 segment
    for (t = mid; t + 8 <= end; t += 8) {
        int e[8];
        float2 v[8];
#pragma unroll
        for (int u = 0; u < 8; u++) e[u] = g_epack[t + u];
#pragma unroll
        for (int u = 0; u < 8; u++) v[u] = proj[e[u] * 64 + 32 + lane];
#pragma unroll
        for (int u = 0; u < 8; u++) { a1.x += v[u].x; a1.y += v[u].y; }
    }
    for (; t < end; t++) {
        float2 v = proj[g_epack[t] * 64 + 32 + lane];
        a1.x += v.x; a1.y += v.y;
    }

    float ic0 = g_invcnt[2 * i], ic1 = g_invcnt[2 * i + 1];
    float2 sv = sel[i * 32 + lane];
    float v0 = sv.x + a0.x * ic0 + a1.x * ic1;
    float v1 = sv.y + a0.y * ic0 + a1.y * ic1;

    float s  = v0 + v1;
    float sq = v0 * v0 + v1 * v1;
#pragma unroll
    for (int off = 16; off; off >>= 1) {
        s  += __shfl_xor_sync(0xffffffffu, s,  off);
        sq += __shfl_xor_sync(0xffffffffu, sq, off);
    }
    float mean = s * (1.0f / 64.0f);
    float var  = sq * (1.0f / 64.0f) - mean * mean;
    float inv  = rsqrtf(var + LN_EPS);
    float2 gm = reinterpret_cast<const float2*>(gamma)[lane];
    float2 bt = reinterpret_cast<const float2*>(beta)[lane];
    v0 = (v0 - mean) * inv * gm.x + bt.x;
    v1 = (v1 - mean) * inv * gm.y + bt.y;

    if (DO_GELU) {
        v0 = 0.5f * v0 * (1.0f + erff(v0 * 0.70710678118654752440f));
        v1 = 0.5f * v1 * (1.0f + erff(v1 * 0.70710678118654752440f));
    }
    out[i * 32 + lane] = make_float2(v0, v1);
}

// ---------------- launcher ----------------------------------------------------
extern "C" void kernel_launch(void* const* d_in, const int* in_sizes, int n_in,
                              void* d_out, int out_size) {
    const float* x     = (const float*)d_in[0];
    const void*  ei    = d_in[1];
    const void*  et    = d_in[2];
    const float* W1    = (const float*)d_in[3];
    const float* root1 = (const float*)d_in[4];
    const float* b1    = (const float*)d_in[5];
    const float* g1    = (const float*)d_in[6];
    const float* be1   = (const float*)d_in[7];
    const float* W2    = (const float*)d_in[8];
    const float* root2 = (const float*)d_in[9];
    const float* b2    = (const float*)d_in[10];
    const float* g2    = (const float*)d_in[11];
    const float* be2   = (const float*)d_in[12];
    float* out = (float*)d_out;

    static cudaStream_t s_aux = nullptr;
    static cudaEvent_t  ev_fork = nullptr, ev_csr = nullptr, ev_g1 = nullptr, ev_b = nullptr;
    if (s_aux == nullptr) {
        cudaStreamCreateWithFlags(&s_aux, cudaStreamNonBlocking);
        cudaEventCreateWithFlags(&ev_fork, cudaEventDisableTiming);
        cudaEventCreateWithFlags(&ev_csr, cudaEventDisableTiming);
        cudaEventCreateWithFlags(&ev_g1, cudaEventDisableTiming);
        cudaEventCreateWithFlags(&ev_b, cudaEventDisableTiming);
    }

    const int GEMM_BLOCKS = (N_NODES + 63) / 64;          // 782
    const int GEMM_A = 391, GEMM_B = GEMM_BLOCKS - GEMM_A;
    const int GATH_BLOCKS = (N_NODES + 7) / 8;            // 6250
    const int GATH_A = 3128, GATH_B = GATH_BLOCKS - GATH_A;
    const int EDGE_BLOCKS = (N_EDGES / 2 + 255) / 256;    // 1563

    // ---- fork: CSR chain on aux; wsplit + gemm1 on main ----
    cudaEventRecord(ev_fork, 0);
    cudaStreamWaitEvent(s_aux, ev_fork, 0);

    zero_sniff_kernel<<<(2 * N_NODES + 255) / 256, 256, 0, s_aux>>>((const int*)ei);
    count_kernel<<<EDGE_BLOCKS, 256, 0, s_aux>>>(ei, et);
    scanAB_kernel<<<SCAN_BLOCKS, 256, 0, s_aux>>>();
    scanC_kernel<<<SCAN_BLOCKS, 256, 0, s_aux>>>();
    scatter_kernel<<<EDGE_BLOCKS, 256, 0, s_aux>>>(ei, et);
    cudaEventRecord(ev_csr, s_aux);

    wsplit_all_kernel<<<(192 * 128 + 192 * 64 + 255) / 256, 256>>>(root1, W1, root2, W2);
    gemm_kernel<128, false, false><<<GEMM_BLOCKS, 256>>>(x, b1, 0);
    cudaEventRecord(ev_g1, 0);

    // ---- pipelined middle: gather1/gemm2 split at node 25024 ----
    cudaStreamWaitEvent(0, ev_csr, 0);
    cudaStreamWaitEvent(s_aux, ev_g1, 0);

    gather_kernel<true, false><<<GATH_A, 256>>>(g1, be1, nullptr, 0);
    gather_kernel<true, false><<<GATH_B, 256, 0, s_aux>>>(g1, be1, nullptr, 25024);

    gemm_kernel<64, true, true><<<GEMM_A, 256>>>(nullptr, b2, 0);
    gemm_kernel<64, true, true><<<GEMM_B, 256, 0, s_aux>>>(nullptr, b2, GEMM_A);

    // ---- join + final gather ----
    cudaEventRecord(ev_b, s_aux);
    cudaStreamWaitEvent(0, ev_b, 0);
    gather_kernel<false, true><<<GATH_BLOCKS, 256>>>(g2, be2, out, 0);
}